// round 15
// baseline (speedup 1.0000x reference)
#include <cuda_runtime.h>
#include <cuda_bf16.h>
#include <math.h>
#include <stdint.h>

// Problem constants
#define NB 8
#define NS 1024
#define ND 768
#define NH 12
#define NHD 64
#define NM (NB*NS)        // 8192 rows
#define NBH (NB*NH)       // 96 batch-head pairs
#define WSZ (ND*ND)       // 589824

#define LOG2E 1.4426950408889634f
#define QSCALE (0.125f * LOG2E)

// ---------------- scratch (static device globals; no allocation) ----------------
__device__ __nv_bfloat16 g_q  [NM*ND];
__device__ __nv_bfloat16 g_k  [NM*ND];
__device__ __nv_bfloat16 g_v  [NM*ND];
__device__ __nv_bfloat16 g_ctx[NM*ND];
__device__ float         g_proj[NM*ND];
__device__ __nv_bfloat16 g_hid[NM*ND];     // hidden pre-converted to bf16
__device__ __nv_bfloat16 g_wb [4*WSZ];     // Wq|Wk|Wv|Wo pre-converted to bf16

// ---------------- helpers ----------------
__device__ __forceinline__ void mma_bf16(float d[4], const uint32_t a[4],
                                         const uint32_t b0, const uint32_t b1) {
    asm volatile(
        "mma.sync.aligned.m16n8k16.row.col.f32.bf16.bf16.f32 "
        "{%0,%1,%2,%3}, {%4,%5,%6,%7}, {%8,%9}, {%0,%1,%2,%3};\n"
        : "+f"(d[0]), "+f"(d[1]), "+f"(d[2]), "+f"(d[3])
        : "r"(a[0]), "r"(a[1]), "r"(a[2]), "r"(a[3]),
          "r"(b0), "r"(b1));
}

__device__ __forceinline__ void ldsm_x4(uint32_t r[4], uint32_t saddr) {
    asm volatile("ldmatrix.sync.aligned.m8n8.x4.shared.b16 {%0,%1,%2,%3}, [%4];"
                 : "=r"(r[0]), "=r"(r[1]), "=r"(r[2]), "=r"(r[3]) : "r"(saddr));
}
__device__ __forceinline__ void ldsm_x4_t(uint32_t r[4], uint32_t saddr) {
    asm volatile("ldmatrix.sync.aligned.m8n8.x4.trans.shared.b16 {%0,%1,%2,%3}, [%4];"
                 : "=r"(r[0]), "=r"(r[1]), "=r"(r[2]), "=r"(r[3]) : "r"(saddr));
}

__device__ __forceinline__ uint32_t pack_bf2(float lo, float hi) {
    __nv_bfloat162 p = __floats2bfloat162_rn(lo, hi);   // .x = lo (low halfword)
    return *(uint32_t*)&p;
}

__device__ __forceinline__ float ex2f(float x) {
    float r;
    asm("ex2.approx.ftz.f32 %0, %1;" : "=f"(r) : "f"(x));
    return r;
}

__device__ __forceinline__ void cp_async16(uint32_t smem_dst, const void* gsrc) {
    asm volatile("cp.async.cg.shared.global [%0], [%1], 16;\n"
                 :: "r"(smem_dst), "l"(gsrc));
}
__device__ __forceinline__ void cp_commit() {
    asm volatile("cp.async.commit_group;\n");
}
__device__ __forceinline__ void cp_wait0() {
    asm volatile("cp.async.wait_group 0;\n");
}

// ---------------- fused fp32 -> bf16 conversion (hidden + 4 weights) --------
#define HID_BLKS (NM*ND/4/256)   // 6144
#define W_BLKS   (WSZ/4/256)     // 576

__global__ __launch_bounds__(256)
void cvt_all_kernel(const float* __restrict__ hid,
                    const float* __restrict__ W0, const float* __restrict__ W1,
                    const float* __restrict__ W2, const float* __restrict__ W3,
                    __nv_bfloat16* __restrict__ hb, __nv_bfloat16* __restrict__ wb)
{
    const int bx = blockIdx.x;
    const float* src;
    __nv_bfloat16* dst;
    long i;
    if (bx < HID_BLKS) {
        i = ((long)bx * 256 + threadIdx.x) * 4;
        src = hid; dst = hb;
    } else {
        const int r = bx - HID_BLKS;
        const int w = r / W_BLKS;
        i = ((long)(r % W_BLKS) * 256 + threadIdx.x) * 4;
        src = (w == 0) ? W0 : (w == 1) ? W1 : (w == 2) ? W2 : W3;
        dst = wb + (long)w * WSZ;
    }
    float4 v = *(const float4*)(src + i);
    *(uint2*)(dst + i) = make_uint2(pack_bf2(v.x, v.y), pack_bf2(v.z, v.w));
}

// ---------------- BF16 GEMM, 2-stage cp.async, BK=64 ------------------------
// C[M,768] = A[M,768] @ W[N,768]^T + bias, epilogue scale. A,W bf16 in gmem.
// BM=BN=128, BK=64 halves (128B/row), 256 thr, 8 warps (warp tile 32x64).
// Row stride 144 B (flash-proven conflict-free LDSM layout). 12 k-steps,
// one cp.async group in flight (round-12 discipline).
#define GK 768
#define BKH 64               // k per stage (halves)
#define GROWB 144            // smem row stride bytes
#define GBUF (128*GROWB)     // 18432 B per operand per stage

template<bool CBF>
__global__ __launch_bounds__(256, 2)
void bf16_gemm_ca2(const __nv_bfloat16* __restrict__ A,
                   const __nv_bfloat16* __restrict__ Wbase, long wstride,
                   const float* __restrict__ b0, const float* __restrict__ b1,
                   const float* __restrict__ b2,
                   void* __restrict__ C0, void* __restrict__ C1,
                   void* __restrict__ C2, int N,
                   float s0, float s1, float s2)
{
    extern __shared__ uint32_t sm[];
    // layout: A stage0 | A stage1 | B stage0 | B stage1, each GBUF bytes
    const int z = blockIdx.z;
    const float* bias = (z == 0) ? b0 : (z == 1) ? b1 : b2;
    void* Cout        = (z == 0) ? C0 : (z == 1) ? C1 : C2;
    const float cscale = (z == 0) ? s0 : (z == 1) ? s1 : s2;
    const __nv_bfloat16* W = Wbase + (long)z * wstride;

    const int t     = threadIdx.x;
    const int warp  = t >> 5;
    const int lane  = t & 31;
    const int warpM = warp >> 1;
    const int warpN = warp & 1;
    const int cRow  = blockIdx.y * 128;
    const int cCol  = blockIdx.x * 128;

    const int aRow  = t >> 2;           // 0..63 (rows r and r+64)
    const int aColB = (t & 3) * 16;     // 0..48 within first 64B half

    const char* Ag = (const char*)(A + (long)(cRow + aRow) * GK) + aColB;
    const char* Wg = (const char*)(W + (long)(cCol + aRow) * GK) + aColB;
    const long ROWSTEP = (long)64 * GK * 2;    // 64 rows in bytes

    const uint32_t sb = (uint32_t)__cvta_generic_to_shared(sm);
    const uint32_t sA = sb + (uint32_t)(aRow * GROWB + aColB);
    const uint32_t sBb = sA + 2 * GBUF;

    // issue one 64-half stage (8 x 16B per thread) into buffer s
    auto issue = [&](int s, int kt) {
        const uint32_t so = (uint32_t)(s * GBUF);
        const long gk = (long)kt * 2;
        cp_async16(sA + so,                    Ag + gk);
        cp_async16(sA + so + 64,               Ag + gk + 64);
        cp_async16(sA + so + 64 * GROWB,       Ag + gk + ROWSTEP);
        cp_async16(sA + so + 64 * GROWB + 64,  Ag + gk + ROWSTEP + 64);
        cp_async16(sBb + so,                   Wg + gk);
        cp_async16(sBb + so + 64,              Wg + gk + 64);
        cp_async16(sBb + so + 64 * GROWB,      Wg + gk + ROWSTEP);
        cp_async16(sBb + so + 64 * GROWB + 64, Wg + gk + ROWSTEP + 64);
        cp_commit();
    };

    issue(0, 0);
    cp_wait0();
    __syncthreads();

    float acc[2][8][4];
    #pragma unroll
    for (int i = 0; i < 2; i++)
        #pragma unroll
        for (int j = 0; j < 8; j++)
            #pragma unroll
            for (int r = 0; r < 4; r++) acc[i][j][r] = 0.f;

    const int lq = lane >> 2;
    const int lr = lane & 3;

    const uint32_t aoff = (uint32_t)((lane & 15) * GROWB + ((lane >> 4) << 4));
    const uint32_t boff = (uint32_t)(((lane & 7) + ((lane >> 4) << 3)) * GROWB
                                     + (((lane >> 3) & 1) << 4));
    const uint32_t aA0 = sb + (uint32_t)(warpM * 32 * GROWB) + aoff;
    const uint32_t bB0 = sb + 2 * GBUF + (uint32_t)(warpN * 64 * GROWB) + boff;

    int buf = 0;
    for (int kt = 0; kt < GK; kt += BKH) {
        const bool more = (kt + BKH) < GK;
        if (more) issue(buf ^ 1, kt + BKH);

        const uint32_t ab  = aA0 + buf * GBUF;
        const uint32_t bb0 = bB0 + buf * GBUF;

        #pragma unroll
        for (int kb = 0; kb < 4; kb++) {
            uint32_t a0[4], a1[4];
            ldsm_x4(a0, ab + kb * 32);
            ldsm_x4(a1, ab + 16 * GROWB + kb * 32);
            #pragma unroll
            for (int nt2 = 0; nt2 < 4; nt2++) {
                uint32_t bbr[4];
                ldsm_x4(bbr, bb0 + nt2 * (16 * GROWB) + kb * 32);
                mma_bf16(acc[0][nt2 * 2],     a0, bbr[0], bbr[1]);
                mma_bf16(acc[0][nt2 * 2 + 1], a0, bbr[2], bbr[3]);
                mma_bf16(acc[1][nt2 * 2],     a1, bbr[0], bbr[1]);
                mma_bf16(acc[1][nt2 * 2 + 1], a1, bbr[2], bbr[3]);
            }
        }

        if (more) cp_wait0();
        __syncthreads();
        buf ^= 1;
    }

    // ---- epilogue: (acc + bias) * cscale ----
    #pragma unroll
    for (int nt = 0; nt < 8; nt++) {
        const int col = cCol + warpN * 64 + nt * 8 + lr * 2;
        const float2 bb = *(const float2*)(bias + col);
        #pragma unroll
        for (int mt = 0; mt < 2; mt++) {
            const int row = cRow + warpM * 32 + mt * 16 + lq;
            float c0 = (acc[mt][nt][0] + bb.x) * cscale;
            float c1 = (acc[mt][nt][1] + bb.y) * cscale;
            float c2 = (acc[mt][nt][2] + bb.x) * cscale;
            float c3 = (acc[mt][nt][3] + bb.y) * cscale;
            if (CBF) {
                __nv_bfloat16* Cb = (__nv_bfloat16*)Cout;
                *(uint32_t*)(Cb + (long)row * N + col)       = pack_bf2(c0, c1);
                *(uint32_t*)(Cb + (long)(row + 8) * N + col) = pack_bf2(c2, c3);
            } else {
                float* Cf = (float*)Cout;
                *(float2*)(Cf + (long)row * N + col)       = make_float2(c0, c1);
                *(float2*)(Cf + (long)(row + 8) * N + col) = make_float2(c2, c3);
            }
        }
    }
}

// ---------------- BF16 flash attention (unchanged from round 13/14) ---------
#define FW 36     // row stride in 32-bit words (72 bf16)
#define ROWB 144  // row stride bytes

__global__ __launch_bounds__(128, 2)
void flash_bf16_kernel(const __nv_bfloat16* __restrict__ Q,
                       const __nv_bfloat16* __restrict__ Kx,
                       const __nv_bfloat16* __restrict__ Vx,
                       const float* __restrict__ mask,
                       const float* __restrict__ head_mask,
                       __nv_bfloat16* __restrict__ Cx)
{
    extern __shared__ uint32_t fsm[];
    float* Ms = (float*)(fsm + 384 * FW);    // [1024] mask row (already *log2e)

    const int bh = blockIdx.y;
    const int b  = bh / NH;
    const int h  = bh % NH;
    const int q0 = blockIdx.x * 128;
    const int t  = threadIdx.x;
    const int warp = t >> 5, lane = t & 31;
    const int lq = lane >> 2, lr = lane & 3;
    const int qrow = warp * 32;

    const __nv_bfloat16* Qg = Q  + (long)b * NS * ND + (long)h * NHD;
    const __nv_bfloat16* Kg = Kx + (long)b * NS * ND + (long)h * NHD;
    const __nv_bfloat16* Vg = Vx + (long)b * NS * ND + (long)h * NHD;

    const uint32_t sb = (uint32_t)__cvta_generic_to_shared(fsm);
    const int seg = t & 7;
    const int rb  = t >> 3;

    {
        #pragma unroll
        for (int i = 0; i < 8; i++) {
            const int r = i * 16 + rb;
            uint4 qv = *(const uint4*)((const char*)(Qg + (long)(q0 + r) * ND) + seg * 16);
            *(uint4*)((char*)fsm + r * ROWB + seg * 16) = qv;
        }
        float4 m0v = *(const float4*)(mask + b * NS + t * 8);
        float4 m1v = *(const float4*)(mask + b * NS + t * 8 + 4);
        m0v.x *= LOG2E; m0v.y *= LOG2E; m0v.z *= LOG2E; m0v.w *= LOG2E;
        m1v.x *= LOG2E; m1v.y *= LOG2E; m1v.z *= LOG2E; m1v.w *= LOG2E;
        *(float4*)&Ms[t * 8]     = m0v;
        *(float4*)&Ms[t * 8 + 4] = m1v;

        #pragma unroll
        for (int i = 0; i < 4; i++) {
            const int r = i * 16 + rb;
            cp_async16(sb + (uint32_t)((128 + r) * ROWB + seg * 16),
                       (const char*)(Kg + (long)r * ND) + seg * 16);
            cp_async16(sb + (uint32_t)((192 + r) * ROWB + seg * 16),
                       (const char*)(Vg + (long)r * ND) + seg * 16);
        }
        cp_commit();
        cp_wait0();
    }
    __syncthreads();

    const uint32_t aoff = (uint32_t)((lane & 15) * ROWB + ((lane >> 4) << 4));
    const uint32_t koff = (uint32_t)(((lane & 7) + ((lane >> 4) << 3)) * ROWB
                                     + (((lane >> 3) & 1) << 4));
    const uint32_t voff = (uint32_t)(((lane & 7) + (((lane >> 3) & 1) << 3)) * ROWB
                                     + ((lane >> 4) << 4));

    const uint32_t qA = sb + (uint32_t)(qrow * ROWB) + aoff;

    uint32_t qf[2][4][4];
    #pragma unroll
    for (int mt = 0; mt < 2; mt++)
        #pragma unroll
        for (int ks = 0; ks < 4; ks++)
            ldsm_x4(qf[mt][ks], qA + mt * (16 * ROWB) + ks * 32);

    float acc_o[2][8][4];
    #pragma unroll
    for (int mt = 0; mt < 2; mt++)
        #pragma unroll
        for (int nt = 0; nt < 8; nt++)
            #pragma unroll
            for (int j = 0; j < 4; j++) acc_o[mt][nt][j] = 0.f;
    float m[4], l[4];
    #pragma unroll
    for (int i = 0; i < 4; i++) { m[i] = -3.4e38f; l[i] = 0.f; }

    int buf = 0;
    for (int it = 0; it < 16; it++) {
        const int k0 = it * 64;
        const bool more = it < 15;

        if (more) {
            const int nbase = 128 + (buf ^ 1) * 128;
            #pragma unroll
            for (int i = 0; i < 4; i++) {
                const int r = i * 16 + rb;
                cp_async16(sb + (uint32_t)((nbase + r) * ROWB + seg * 16),
                           (const char*)(Kg + (long)(k0 + 64 + r) * ND) + seg * 16);
                cp_async16(sb + (uint32_t)((nbase + 64 + r) * ROWB + seg * 16),
                           (const char*)(Vg + (long)(k0 + 64 + r) * ND) + seg * 16);
            }
            cp_commit();
        }

        const uint32_t kB = sb + (uint32_t)((128 + buf * 128) * ROWB) + koff;
        const uint32_t vB = sb + (uint32_t)((192 + buf * 128) * ROWB) + voff;

        float acc_s[2][8][4];
        #pragma unroll
        for (int mt = 0; mt < 2; mt++)
            #pragma unroll
            for (int nt = 0; nt < 8; nt++)
                #pragma unroll
                for (int j = 0; j < 4; j++) acc_s[mt][nt][j] = 0.f;

        #pragma unroll
        for (int ks = 0; ks < 4; ks++) {
            #pragma unroll
            for (int nt2 = 0; nt2 < 4; nt2++) {
                uint32_t bb[4];
                ldsm_x4(bb, kB + nt2 * (16 * ROWB) + ks * 32);
                mma_bf16(acc_s[0][nt2 * 2],     qf[0][ks], bb[0], bb[1]);
                mma_bf16(acc_s[0][nt2 * 2 + 1], qf[0][ks], bb[2], bb[3]);
                mma_bf16(acc_s[1][nt2 * 2],     qf[1][ks], bb[0], bb[1]);
                mma_bf16(acc_s[1][nt2 * 2 + 1], qf[1][ks], bb[2], bb[3]);
            }
        }

        uint32_t pf[2][8][2];
        #pragma unroll
        for (int mt = 0; mt < 2; mt++) {
            float mx0 = -3.4e38f, mx1 = -3.4e38f;
            #pragma unroll
            for (int nt = 0; nt < 8; nt++) {
                float2 mk = *(const float2*)&Ms[k0 + nt * 8 + lr * 2];
                acc_s[mt][nt][0] += mk.x;
                acc_s[mt][nt][1] += mk.y;
                acc_s[mt][nt][2] += mk.x;
                acc_s[mt][nt][3] += mk.y;
                mx0 = fmaxf(mx0, fmaxf(acc_s[mt][nt][0], acc_s[mt][nt][1]));
                mx1 = fmaxf(mx1, fmaxf(acc_s[mt][nt][2], acc_s[mt][nt][3]));
            }
            mx0 = fmaxf(mx0, __shfl_xor_sync(0xffffffffu, mx0, 1));
            mx0 = fmaxf(mx0, __shfl_xor_sync(0xffffffffu, mx0, 2));
            mx1 = fmaxf(mx1, __shfl_xor_sync(0xffffffffu, mx1, 1));
            mx1 = fmaxf(mx1, __shfl_xor_sync(0xffffffffu, mx1, 2));

            const float mn0 = fmaxf(m[mt * 2 + 0], mx0);
            const float mn1 = fmaxf(m[mt * 2 + 1], mx1);
            const float corr0 = ex2f(m[mt * 2 + 0] - mn0);
            const float corr1 = ex2f(m[mt * 2 + 1] - mn1);
            m[mt * 2 + 0] = mn0;
            m[mt * 2 + 1] = mn1;

            float ls0 = 0.f, ls1 = 0.f;
            #pragma unroll
            for (int nt = 0; nt < 8; nt++) {
                __nv_bfloat162 pb0 = __floats2bfloat162_rn(ex2f(acc_s[mt][nt][0] - mn0),
                                                           ex2f(acc_s[mt][nt][1] - mn0));
                __nv_bfloat162 pb1 = __floats2bfloat162_rn(ex2f(acc_s[mt][nt][2] - mn1),
                                                           ex2f(acc_s[mt][nt][3] - mn1));
                ls0 += __bfloat162float(pb0.x) + __bfloat162float(pb0.y);
                ls1 += __bfloat162float(pb1.x) + __bfloat162float(pb1.y);
                pf[mt][nt][0] = *(uint32_t*)&pb0;
                pf[mt][nt][1] = *(uint32_t*)&pb1;
            }
            ls0 += __shfl_xor_sync(0xffffffffu, ls0, 1);
            ls0 += __shfl_xor_sync(0xffffffffu, ls0, 2);
            ls1 += __shfl_xor_sync(0xffffffffu, ls1, 1);
            ls1 += __shfl_xor_sync(0xffffffffu, ls1, 2);
            l[mt * 2 + 0] = l[mt * 2 + 0] * corr0 + ls0;
            l[mt * 2 + 1] = l[mt * 2 + 1] * corr1 + ls1;

            #pragma unroll
            for (int nt = 0; nt < 8; nt++) {
                acc_o[mt][nt][0] *= corr0;
                acc_o[mt][nt][1] *= corr0;
                acc_o[mt][nt][2] *= corr1;
                acc_o[mt][nt][3] *= corr1;
            }
        }

        #pragma unroll
        for (int kb = 0; kb < 4; kb++) {
            uint32_t a0[4] = {pf[0][2*kb][0], pf[0][2*kb][1],
                              pf[0][2*kb+1][0], pf[0][2*kb+1][1]};
            uint32_t a1[4] = {pf[1][2*kb][0], pf[1][2*kb][1],
                              pf[1][2*kb+1][0], pf[1][2*kb+1][1]};
            #pragma unroll
            for (int nd2 = 0; nd2 < 4; nd2++) {
                uint32_t bb[4];
                ldsm_x4_t(bb, vB + kb * (16 * ROWB) + nd2 * 32);
                mma_bf16(acc_o[0][nd2 * 2],     a0, bb[0], bb[1]);
                mma_bf16(acc_o[0][nd2 * 2 + 1], a0, bb[2], bb[3]);
                mma_bf16(acc_o[1][nd2 * 2],     a1, bb[0], bb[1]);
                mma_bf16(acc_o[1][nd2 * 2 + 1], a1, bb[2], bb[3]);
            }
        }

        if (more) cp_wait0();
        __syncthreads();
        buf ^= 1;
    }

    const float hm = head_mask[h];
    #pragma unroll
    for (int mt = 0; mt < 2; mt++) {
        const float inv0 = hm / l[mt * 2 + 0];
        const float inv1 = hm / l[mt * 2 + 1];
        #pragma unroll
        for (int nt = 0; nt < 8; nt++) {
            const int col = h * NHD + nt * 8 + lr * 2;
            const long r0 = (long)b * NS + q0 + qrow + mt * 16 + lq;
            *(uint32_t*)(Cx + r0 * ND + col) =
                pack_bf2(acc_o[mt][nt][0] * inv0, acc_o[mt][nt][1] * inv0);
            *(uint32_t*)(Cx + (r0 + 8) * ND + col) =
                pack_bf2(acc_o[mt][nt][2] * inv1, acc_o[mt][nt][3] * inv1);
        }
    }
}

// ---------------- residual + LayerNorm (192 threads, float4) ----------------
__global__ __launch_bounds__(192)
void ln_kernel(const float* __restrict__ proj, const float* __restrict__ hidden,
               const float* __restrict__ gamma, const float* __restrict__ beta,
               float* __restrict__ out)
{
    __shared__ float sred[6];
    const long row = blockIdx.x;
    const int t = threadIdx.x;
    const long base = row * ND + t * 4;

    float4 p = *(const float4*)(proj + base);
    float4 hh = *(const float4*)(hidden + base);
    float4 x = make_float4(p.x + hh.x, p.y + hh.y, p.z + hh.z, p.w + hh.w);

    // block reduction over 6 warps
    auto bsum = [&](float v) -> float {
        #pragma unroll
        for (int o = 16; o; o >>= 1) v += __shfl_xor_sync(0xffffffffu, v, o);
        __syncthreads();
        if ((t & 31) == 0) sred[t >> 5] = v;
        __syncthreads();
        float tot = sred[0] + sred[1] + sred[2] + sred[3] + sred[4] + sred[5];
        return tot;
    };

    float mu = bsum(x.x + x.y + x.z + x.w) * (1.0f / ND);
    float dx = x.x - mu, dy = x.y - mu, dz = x.z - mu, dw = x.w - mu;
    float var = bsum(dx * dx + dy * dy + dz * dz + dw * dw) * (1.0f / ND);
    float rstd = rsqrtf(var + 1e-12f);

    float4 g = *(const float4*)(gamma + t * 4);
    float4 bb = *(const float4*)(beta + t * 4);
    float4 o = make_float4(dx * rstd * g.x + bb.x, dy * rstd * g.y + bb.y,
                           dz * rstd * g.z + bb.z, dw * rstd * g.w + bb.w);
    *(float4*)(out + base) = o;
}

// ---------------- launch ----------------
extern "C" void kernel_launch(void* const* d_in, const int* in_sizes, int n_in,
                              void* d_out, int out_size)
{
    const float* hidden    = (const float*)d_in[0];
    const float* attn_mask = (const float*)d_in[1];
    const float* head_mask = (const float*)d_in[2];
    const float* Wq = (const float*)d_in[3];
    const float* bq = (const float*)d_in[4];
    const float* Wk = (const float*)d_in[5];
    const float* bk = (const float*)d_in[6];
    const float* Wv = (const float*)d_in[7];
    const float* bv = (const float*)d_in[8];
    const float* Wo = (const float*)d_in[9];
    const float* bo = (const float*)d_in[10];
    const float* gamma = (const float*)d_in[11];
    const float* beta  = (const float*)d_in[12];
    float* out = (float*)d_out;

    void *pq, *pk, *pv, *pc, *pp, *ph, *pw;
    cudaGetSymbolAddress(&pq, g_q);
    cudaGetSymbolAddress(&pk, g_k);
    cudaGetSymbolAddress(&pv, g_v);
    cudaGetSymbolAddress(&pc, g_ctx);
    cudaGetSymbolAddress(&pp, g_proj);
    cudaGetSymbolAddress(&ph, g_hid);
    cudaGetSymbolAddress(&pw, g_wb);
    __nv_bfloat16* q   = (__nv_bfloat16*)pq;
    __nv_bfloat16* k   = (__nv_bfloat16*)pk;
    __nv_bfloat16* v   = (__nv_bfloat16*)pv;
    __nv_bfloat16* cx  = (__nv_bfloat16*)pc;
    float*         pr  = (float*)pp;
    __nv_bfloat16* hb  = (__nv_bfloat16*)ph;
    __nv_bfloat16* wb  = (__nv_bfloat16*)pw;

    const int FLASH_SMEM = 384 * FW * 4 + 4096;   // 59392 B
    const int GEMM_SMEM  = 4 * GBUF;              // 73728 B
    static int attr_set = 0;
    if (!attr_set) {
        cudaFuncSetAttribute(flash_bf16_kernel,
                             cudaFuncAttributeMaxDynamicSharedMemorySize, FLASH_SMEM);
        cudaFuncSetAttribute(bf16_gemm_ca2<true>,
                             cudaFuncAttributeMaxDynamicSharedMemorySize, GEMM_SMEM);
        cudaFuncSetAttribute(bf16_gemm_ca2<false>,
                             cudaFuncAttributeMaxDynamicSharedMemorySize, GEMM_SMEM);
        attr_set = 1;
    }

    // fused pre-conversion: hidden + 4 weight matrices -> bf16
    cvt_all_kernel<<<HID_BLKS + 4 * W_BLKS, 256>>>(hidden, Wq, Wk, Wv, Wo, hb, wb);

    // fused QKV: q scaled by 0.125*log2e in epilogue (softmax exp2 domain)
    dim3 gQKV(ND / 128, NM / 128, 3);   // (6, 64, 3)
    bf16_gemm_ca2<true><<<gQKV, 256, GEMM_SMEM>>>(
        hb, wb, (long)WSZ, bq, bk, bv, q, k, v, ND, QSCALE, 1.0f, 1.0f);

    dim3 gF(NS / 128, NBH);             // (8, 96)
    flash_bf16_kernel<<<gF, 128, FLASH_SMEM>>>(q, k, v, attn_mask, head_mask, cx);

    dim3 gO(ND / 128, NM / 128, 1);     // (6, 64, 1)
    bf16_gemm_ca2<false><<<gO, 256, GEMM_SMEM>>>(
        cx, wb + 3 * WSZ, 0L, bo, bo, bo, pr, pr, pr, ND, 1.0f, 1.0f, 1.0f);

    ln_kernel<<<NM, 192>>>(pr, hidden, gamma, beta, out);
}

// round 16
// speedup vs baseline: 1.0695x; 1.0695x over previous
#include <cuda_runtime.h>
#include <cuda_bf16.h>
#include <math.h>
#include <stdint.h>

// Problem constants
#define NB 8
#define NS 1024
#define ND 768
#define NH 12
#define NHD 64
#define NM (NB*NS)        // 8192 rows
#define NBH (NB*NH)       // 96 batch-head pairs
#define WSZ (ND*ND)       // 589824

#define LOG2E 1.4426950408889634f
#define QSCALE (0.125f * LOG2E)

// ---------------- scratch (static device globals; no allocation) ----------------
__device__ __nv_bfloat16 g_q  [NM*ND];
__device__ __nv_bfloat16 g_k  [NM*ND];
__device__ __nv_bfloat16 g_v  [NM*ND];
__device__ __nv_bfloat16 g_ctx[NM*ND];
__device__ float         g_proj[NM*ND];
__device__ __nv_bfloat16 g_hid[NM*ND];     // hidden pre-converted to bf16
__device__ __nv_bfloat16 g_wb [4*WSZ];     // Wq|Wk|Wv|Wo pre-converted to bf16

// ---------------- helpers ----------------
__device__ __forceinline__ void mma_bf16(float d[4], const uint32_t a[4],
                                         const uint32_t b0, const uint32_t b1) {
    asm volatile(
        "mma.sync.aligned.m16n8k16.row.col.f32.bf16.bf16.f32 "
        "{%0,%1,%2,%3}, {%4,%5,%6,%7}, {%8,%9}, {%0,%1,%2,%3};\n"
        : "+f"(d[0]), "+f"(d[1]), "+f"(d[2]), "+f"(d[3])
        : "r"(a[0]), "r"(a[1]), "r"(a[2]), "r"(a[3]),
          "r"(b0), "r"(b1));
}

__device__ __forceinline__ void ldsm_x4(uint32_t r[4], uint32_t saddr) {
    asm volatile("ldmatrix.sync.aligned.m8n8.x4.shared.b16 {%0,%1,%2,%3}, [%4];"
                 : "=r"(r[0]), "=r"(r[1]), "=r"(r[2]), "=r"(r[3]) : "r"(saddr));
}
__device__ __forceinline__ void ldsm_x4_t(uint32_t r[4], uint32_t saddr) {
    asm volatile("ldmatrix.sync.aligned.m8n8.x4.trans.shared.b16 {%0,%1,%2,%3}, [%4];"
                 : "=r"(r[0]), "=r"(r[1]), "=r"(r[2]), "=r"(r[3]) : "r"(saddr));
}

__device__ __forceinline__ uint32_t pack_bf2(float lo, float hi) {
    __nv_bfloat162 p = __floats2bfloat162_rn(lo, hi);   // .x = lo (low halfword)
    return *(uint32_t*)&p;
}

__device__ __forceinline__ float ex2f(float x) {
    float r;
    asm("ex2.approx.ftz.f32 %0, %1;" : "=f"(r) : "f"(x));
    return r;
}

__device__ __forceinline__ void cp_async16(uint32_t smem_dst, const void* gsrc) {
    asm volatile("cp.async.cg.shared.global [%0], [%1], 16;\n"
                 :: "r"(smem_dst), "l"(gsrc));
}
__device__ __forceinline__ void cp_commit() {
    asm volatile("cp.async.commit_group;\n");
}
__device__ __forceinline__ void cp_wait0() {
    asm volatile("cp.async.wait_group 0;\n");
}
__device__ __forceinline__ void cp_wait1() {
    asm volatile("cp.async.wait_group 1;\n");
}

// ---------------- fused fp32 -> bf16 conversion (hidden + 4 weights) --------
#define HID_BLKS (NM*ND/4/256)   // 6144
#define W_BLKS   (WSZ/4/256)     // 576

__global__ __launch_bounds__(256)
void cvt_all_kernel(const float* __restrict__ hid,
                    const float* __restrict__ W0, const float* __restrict__ W1,
                    const float* __restrict__ W2, const float* __restrict__ W3,
                    __nv_bfloat16* __restrict__ hb, __nv_bfloat16* __restrict__ wb)
{
    const int bx = blockIdx.x;
    const float* src;
    __nv_bfloat16* dst;
    long i;
    if (bx < HID_BLKS) {
        i = ((long)bx * 256 + threadIdx.x) * 4;
        src = hid; dst = hb;
    } else {
        const int r = bx - HID_BLKS;
        const int w = r / W_BLKS;
        i = ((long)(r % W_BLKS) * 256 + threadIdx.x) * 4;
        src = (w == 0) ? W0 : (w == 1) ? W1 : (w == 2) ? W2 : W3;
        dst = wb + (long)w * WSZ;
    }
    float4 v = *(const float4*)(src + i);
    *(uint2*)(dst + i) = make_uint2(pack_bf2(v.x, v.y), pack_bf2(v.z, v.w));
}

// ---------------- BF16 GEMM, 3-stage cp.async pipeline (round-14 proven) ----
#define GK 768
#define BKH 32             // k per stage (halves)
#define NKS (GK/BKH)       // 24 k-steps
#define BSW 20             // smem row stride in 32-bit words
#define ROWB2 80           // smem row stride bytes
#define BUFB2 (128*ROWB2)  // 10240 B per operand per stage

template<bool CBF>
__global__ __launch_bounds__(256, 2)
void bf16_gemm_ca3(const __nv_bfloat16* __restrict__ A,
                   const __nv_bfloat16* __restrict__ Wbase, long wstride,
                   const float* __restrict__ b0, const float* __restrict__ b1,
                   const float* __restrict__ b2,
                   void* __restrict__ C0, void* __restrict__ C1,
                   void* __restrict__ C2, int N,
                   float s0, float s1, float s2)
{
    extern __shared__ uint32_t sm[];
    // layout: A stages [3][128][20w] | B stages [3][128][20w]
    const int z = blockIdx.z;
    const float* bias = (z == 0) ? b0 : (z == 1) ? b1 : b2;
    void* Cout        = (z == 0) ? C0 : (z == 1) ? C1 : C2;
    const float cscale = (z == 0) ? s0 : (z == 1) ? s1 : s2;
    const __nv_bfloat16* W = Wbase + (long)z * wstride;

    const int t     = threadIdx.x;
    const int warp  = t >> 5;
    const int lane  = t & 31;
    const int warpM = warp >> 1;
    const int warpN = warp & 1;
    const int cRow  = blockIdx.y * 128;
    const int cCol  = blockIdx.x * 128;

    const int aRow  = t >> 2;           // 0..63 (2 passes of 64 rows)
    const int aColB = (t & 3) * 16;     // byte col within 64B k-slab

    const char* Ag = (const char*)(A + (long)(cRow + aRow) * GK) + aColB;
    const char* Wg = (const char*)(W + (long)(cCol + aRow) * GK) + aColB;
    const long ROWSTEP = (long)64 * GK * 2;

    const uint32_t sb = (uint32_t)__cvta_generic_to_shared(sm);
    const uint32_t sA = sb + (uint32_t)(aRow * ROWB2 + aColB);
    const uint32_t sBb = sA + 3 * BUFB2;

    // issue stage s (k offset = s-th BKH slab) into buffer s%3
    auto issue = [&](int s) {
        const uint32_t so = (uint32_t)((s % 3) * BUFB2);
        const long gk = (long)s * BKH * 2;
        cp_async16(sA + so,               Ag + gk);
        cp_async16(sA + so + 64 * ROWB2,  Ag + gk + ROWSTEP);
        cp_async16(sBb + so,              Wg + gk);
        cp_async16(sBb + so + 64 * ROWB2, Wg + gk + ROWSTEP);
        cp_commit();
    };

    // prologue: stages 0 and 1 in flight; wait for stage 0
    issue(0);
    issue(1);
    cp_wait1();
    __syncthreads();

    float acc[2][8][4];
    #pragma unroll
    for (int i = 0; i < 2; i++)
        #pragma unroll
        for (int j = 0; j < 8; j++)
            #pragma unroll
            for (int r = 0; r < 4; r++) acc[i][j][r] = 0.f;

    const int lq = lane >> 2;
    const int lr = lane & 3;

    const uint32_t aoff = (uint32_t)((lane & 15) * ROWB2 + ((lane >> 4) << 4));
    const uint32_t boff = (uint32_t)(((lane & 7) + ((lane >> 4) << 3)) * ROWB2
                                     + (((lane >> 3) & 1) << 4));
    const uint32_t aA0 = sb + (uint32_t)(warpM * 32 * ROWB2) + aoff;
    const uint32_t bB0 = sb + 3 * BUFB2 + (uint32_t)(warpN * 64 * ROWB2) + boff;

    for (int i = 0; i < NKS; i++) {
        // buffer (i+2)%3 held stage i-1; consumption sealed by iter i-1 barrier.
        if (i + 2 < NKS) issue(i + 2);

        const uint32_t bufo = (uint32_t)((i % 3) * BUFB2);
        const uint32_t ab   = aA0 + bufo;
        const uint32_t bb0  = bB0 + bufo;

        #pragma unroll
        for (int kb = 0; kb < 2; kb++) {
            uint32_t a0[4], a1[4];
            ldsm_x4(a0, ab + kb * 32);
            ldsm_x4(a1, ab + 16 * ROWB2 + kb * 32);
            #pragma unroll
            for (int nt2 = 0; nt2 < 4; nt2++) {
                uint32_t bbr[4];
                ldsm_x4(bbr, bb0 + nt2 * (16 * ROWB2) + kb * 32);
                mma_bf16(acc[0][nt2 * 2],     a0, bbr[0], bbr[1]);
                mma_bf16(acc[0][nt2 * 2 + 1], a0, bbr[2], bbr[3]);
                mma_bf16(acc[1][nt2 * 2],     a1, bbr[0], bbr[1]);
                mma_bf16(acc[1][nt2 * 2 + 1], a1, bbr[2], bbr[3]);
            }
        }

        // pending: s(i+1) [+ s(i+2) if issued]. Guarantee s(i+1) ready.
        if (i + 2 < NKS)      cp_wait1();
        else if (i + 1 < NKS) cp_wait0();
        __syncthreads();
    }

    // ---- epilogue: (acc + bias) * cscale ----
    #pragma unroll
    for (int nt = 0; nt < 8; nt++) {
        const int col = cCol + warpN * 64 + nt * 8 + lr * 2;
        const float2 bb = *(const float2*)(bias + col);
        #pragma unroll
        for (int mt = 0; mt < 2; mt++) {
            const int row = cRow + warpM * 32 + mt * 16 + lq;
            float c0 = (acc[mt][nt][0] + bb.x) * cscale;
            float c1 = (acc[mt][nt][1] + bb.y) * cscale;
            float c2 = (acc[mt][nt][2] + bb.x) * cscale;
            float c3 = (acc[mt][nt][3] + bb.y) * cscale;
            if (CBF) {
                __nv_bfloat16* Cb = (__nv_bfloat16*)Cout;
                *(uint32_t*)(Cb + (long)row * N + col)       = pack_bf2(c0, c1);
                *(uint32_t*)(Cb + (long)(row + 8) * N + col) = pack_bf2(c2, c3);
            } else {
                float* Cf = (float*)Cout;
                *(float2*)(Cf + (long)row * N + col)       = make_float2(c0, c1);
                *(float2*)(Cf + (long)(row + 8) * N + col) = make_float2(c2, c3);
            }
        }
    }
}

// ---------------- BF16 flash attention (round-13/14 proven) -----------------
#define FW 36     // row stride in 32-bit words (72 bf16)
#define ROWB 144  // row stride bytes

__global__ __launch_bounds__(128, 2)
void flash_bf16_kernel(const __nv_bfloat16* __restrict__ Q,
                       const __nv_bfloat16* __restrict__ Kx,
                       const __nv_bfloat16* __restrict__ Vx,
                       const float* __restrict__ mask,
                       const float* __restrict__ head_mask,
                       __nv_bfloat16* __restrict__ Cx)
{
    extern __shared__ uint32_t fsm[];
    float* Ms = (float*)(fsm + 384 * FW);    // [1024] mask row (already *log2e)

    const int bh = blockIdx.y;
    const int b  = bh / NH;
    const int h  = bh % NH;
    const int q0 = blockIdx.x * 128;
    const int t  = threadIdx.x;
    const int warp = t >> 5, lane = t & 31;
    const int lq = lane >> 2, lr = lane & 3;
    const int qrow = warp * 32;

    const __nv_bfloat16* Qg = Q  + (long)b * NS * ND + (long)h * NHD;
    const __nv_bfloat16* Kg = Kx + (long)b * NS * ND + (long)h * NHD;
    const __nv_bfloat16* Vg = Vx + (long)b * NS * ND + (long)h * NHD;

    const uint32_t sb = (uint32_t)__cvta_generic_to_shared(fsm);
    const int seg = t & 7;
    const int rb  = t >> 3;

    {
        #pragma unroll
        for (int i = 0; i < 8; i++) {
            const int r = i * 16 + rb;
            uint4 qv = *(const uint4*)((const char*)(Qg + (long)(q0 + r) * ND) + seg * 16);
            *(uint4*)((char*)fsm + r * ROWB + seg * 16) = qv;
        }
        float4 m0v = *(const float4*)(mask + b * NS + t * 8);
        float4 m1v = *(const float4*)(mask + b * NS + t * 8 + 4);
        m0v.x *= LOG2E; m0v.y *= LOG2E; m0v.z *= LOG2E; m0v.w *= LOG2E;
        m1v.x *= LOG2E; m1v.y *= LOG2E; m1v.z *= LOG2E; m1v.w *= LOG2E;
        *(float4*)&Ms[t * 8]     = m0v;
        *(float4*)&Ms[t * 8 + 4] = m1v;

        #pragma unroll
        for (int i = 0; i < 4; i++) {
            const int r = i * 16 + rb;
            cp_async16(sb + (uint32_t)((128 + r) * ROWB + seg * 16),
                       (const char*)(Kg + (long)r * ND) + seg * 16);
            cp_async16(sb + (uint32_t)((192 + r) * ROWB + seg * 16),
                       (const char*)(Vg + (long)r * ND) + seg * 16);
        }
        cp_commit();
        cp_wait0();
    }
    __syncthreads();

    const uint32_t aoff = (uint32_t)((lane & 15) * ROWB + ((lane >> 4) << 4));
    const uint32_t koff = (uint32_t)(((lane & 7) + ((lane >> 4) << 3)) * ROWB
                                     + (((lane >> 3) & 1) << 4));
    const uint32_t voff = (uint32_t)(((lane & 7) + (((lane >> 3) & 1) << 3)) * ROWB
                                     + ((lane >> 4) << 4));

    const uint32_t qA = sb + (uint32_t)(qrow * ROWB) + aoff;

    uint32_t qf[2][4][4];
    #pragma unroll
    for (int mt = 0; mt < 2; mt++)
        #pragma unroll
        for (int ks = 0; ks < 4; ks++)
            ldsm_x4(qf[mt][ks], qA + mt * (16 * ROWB) + ks * 32);

    float acc_o[2][8][4];
    #pragma unroll
    for (int mt = 0; mt < 2; mt++)
        #pragma unroll
        for (int nt = 0; nt < 8; nt++)
            #pragma unroll
            for (int j = 0; j < 4; j++) acc_o[mt][nt][j] = 0.f;
    float m[4], l[4];
    #pragma unroll
    for (int i = 0; i < 4; i++) { m[i] = -3.4e38f; l[i] = 0.f; }

    int buf = 0;
    for (int it = 0; it < 16; it++) {
        const int k0 = it * 64;
        const bool more = it < 15;

        if (more) {
            const int nbase = 128 + (buf ^ 1) * 128;
            #pragma unroll
            for (int i = 0; i < 4; i++) {
                const int r = i * 16 + rb;
                cp_async16(sb + (uint32_t)((nbase + r) * ROWB + seg * 16),
                           (const char*)(Kg + (long)(k0 + 64 + r) * ND) + seg * 16);
                cp_async16(sb + (uint32_t)((nbase + 64 + r) * ROWB + seg * 16),
                           (const char*)(Vg + (long)(k0 + 64 + r) * ND) + seg * 16);
            }
            cp_commit();
        }

        const uint32_t kB = sb + (uint32_t)((128 + buf * 128) * ROWB) + koff;
        const uint32_t vB = sb + (uint32_t)((192 + buf * 128) * ROWB) + voff;

        float acc_s[2][8][4];
        #pragma unroll
        for (int mt = 0; mt < 2; mt++)
            #pragma unroll
            for (int nt = 0; nt < 8; nt++)
                #pragma unroll
                for (int j = 0; j < 4; j++) acc_s[mt][nt][j] = 0.f;

        #pragma unroll
        for (int ks = 0; ks < 4; ks++) {
            #pragma unroll
            for (int nt2 = 0; nt2 < 4; nt2++) {
                uint32_t bb[4];
                ldsm_x4(bb, kB + nt2 * (16 * ROWB) + ks * 32);
                mma_bf16(acc_s[0][nt2 * 2],     qf[0][ks], bb[0], bb[1]);
                mma_bf16(acc_s[0][nt2 * 2 + 1], qf[0][ks], bb[2], bb[3]);
                mma_bf16(acc_s[1][nt2 * 2],     qf[1][ks], bb[0], bb[1]);
                mma_bf16(acc_s[1][nt2 * 2 + 1], qf[1][ks], bb[2], bb[3]);
            }
        }

        uint32_t pf[2][8][2];
        #pragma unroll
        for (int mt = 0; mt < 2; mt++) {
            float mx0 = -3.4e38f, mx1 = -3.4e38f;
            #pragma unroll
            for (int nt = 0; nt < 8; nt++) {
                float2 mk = *(const float2*)&Ms[k0 + nt * 8 + lr * 2];
                acc_s[mt][nt][0] += mk.x;
                acc_s[mt][nt][1] += mk.y;
                acc_s[mt][nt][2] += mk.x;
                acc_s[mt][nt][3] += mk.y;
                mx0 = fmaxf(mx0, fmaxf(acc_s[mt][nt][0], acc_s[mt][nt][1]));
                mx1 = fmaxf(mx1, fmaxf(acc_s[mt][nt][2], acc_s[mt][nt][3]));
            }
            mx0 = fmaxf(mx0, __shfl_xor_sync(0xffffffffu, mx0, 1));
            mx0 = fmaxf(mx0, __shfl_xor_sync(0xffffffffu, mx0, 2));
            mx1 = fmaxf(mx1, __shfl_xor_sync(0xffffffffu, mx1, 1));
            mx1 = fmaxf(mx1, __shfl_xor_sync(0xffffffffu, mx1, 2));

            const float mn0 = fmaxf(m[mt * 2 + 0], mx0);
            const float mn1 = fmaxf(m[mt * 2 + 1], mx1);
            const float corr0 = ex2f(m[mt * 2 + 0] - mn0);
            const float corr1 = ex2f(m[mt * 2 + 1] - mn1);
            m[mt * 2 + 0] = mn0;
            m[mt * 2 + 1] = mn1;

            float ls0 = 0.f, ls1 = 0.f;
            #pragma unroll
            for (int nt = 0; nt < 8; nt++) {
                __nv_bfloat162 pb0 = __floats2bfloat162_rn(ex2f(acc_s[mt][nt][0] - mn0),
                                                           ex2f(acc_s[mt][nt][1] - mn0));
                __nv_bfloat162 pb1 = __floats2bfloat162_rn(ex2f(acc_s[mt][nt][2] - mn1),
                                                           ex2f(acc_s[mt][nt][3] - mn1));
                ls0 += __bfloat162float(pb0.x) + __bfloat162float(pb0.y);
                ls1 += __bfloat162float(pb1.x) + __bfloat162float(pb1.y);
                pf[mt][nt][0] = *(uint32_t*)&pb0;
                pf[mt][nt][1] = *(uint32_t*)&pb1;
            }
            ls0 += __shfl_xor_sync(0xffffffffu, ls0, 1);
            ls0 += __shfl_xor_sync(0xffffffffu, ls0, 2);
            ls1 += __shfl_xor_sync(0xffffffffu, ls1, 1);
            ls1 += __shfl_xor_sync(0xffffffffu, ls1, 2);
            l[mt * 2 + 0] = l[mt * 2 + 0] * corr0 + ls0;
            l[mt * 2 + 1] = l[mt * 2 + 1] * corr1 + ls1;

            #pragma unroll
            for (int nt = 0; nt < 8; nt++) {
                acc_o[mt][nt][0] *= corr0;
                acc_o[mt][nt][1] *= corr0;
                acc_o[mt][nt][2] *= corr1;
                acc_o[mt][nt][3] *= corr1;
            }
        }

        #pragma unroll
        for (int kb = 0; kb < 4; kb++) {
            uint32_t a0[4] = {pf[0][2*kb][0], pf[0][2*kb][1],
                              pf[0][2*kb+1][0], pf[0][2*kb+1][1]};
            uint32_t a1[4] = {pf[1][2*kb][0], pf[1][2*kb][1],
                              pf[1][2*kb+1][0], pf[1][2*kb+1][1]};
            #pragma unroll
            for (int nd2 = 0; nd2 < 4; nd2++) {
                uint32_t bb[4];
                ldsm_x4_t(bb, vB + kb * (16 * ROWB) + nd2 * 32);
                mma_bf16(acc_o[0][nd2 * 2],     a0, bb[0], bb[1]);
                mma_bf16(acc_o[0][nd2 * 2 + 1], a0, bb[2], bb[3]);
                mma_bf16(acc_o[1][nd2 * 2],     a1, bb[0], bb[1]);
                mma_bf16(acc_o[1][nd2 * 2 + 1], a1, bb[2], bb[3]);
            }
        }

        if (more) cp_wait0();
        __syncthreads();
        buf ^= 1;
    }

    const float hm = head_mask[h];
    #pragma unroll
    for (int mt = 0; mt < 2; mt++) {
        const float inv0 = hm / l[mt * 2 + 0];
        const float inv1 = hm / l[mt * 2 + 1];
        #pragma unroll
        for (int nt = 0; nt < 8; nt++) {
            const int col = h * NHD + nt * 8 + lr * 2;
            const long r0 = (long)b * NS + q0 + qrow + mt * 16 + lq;
            *(uint32_t*)(Cx + r0 * ND + col) =
                pack_bf2(acc_o[mt][nt][0] * inv0, acc_o[mt][nt][1] * inv0);
            *(uint32_t*)(Cx + (r0 + 8) * ND + col) =
                pack_bf2(acc_o[mt][nt][2] * inv1, acc_o[mt][nt][3] * inv1);
        }
    }
}

// ---------------- residual + LayerNorm (192 threads, float4) ----------------
__global__ __launch_bounds__(192)
void ln_kernel(const float* __restrict__ proj, const float* __restrict__ hidden,
               const float* __restrict__ gamma, const float* __restrict__ beta,
               float* __restrict__ out)
{
    __shared__ float sred[6];
    const long row = blockIdx.x;
    const int t = threadIdx.x;
    const long base = row * ND + t * 4;

    float4 p = *(const float4*)(proj + base);
    float4 hh = *(const float4*)(hidden + base);
    float4 x = make_float4(p.x + hh.x, p.y + hh.y, p.z + hh.z, p.w + hh.w);

    auto bsum = [&](float v) -> float {
        #pragma unroll
        for (int o = 16; o; o >>= 1) v += __shfl_xor_sync(0xffffffffu, v, o);
        __syncthreads();
        if ((t & 31) == 0) sred[t >> 5] = v;
        __syncthreads();
        return sred[0] + sred[1] + sred[2] + sred[3] + sred[4] + sred[5];
    };

    float mu = bsum(x.x + x.y + x.z + x.w) * (1.0f / ND);
    float dx = x.x - mu, dy = x.y - mu, dz = x.z - mu, dw = x.w - mu;
    float var = bsum(dx * dx + dy * dy + dz * dz + dw * dw) * (1.0f / ND);
    float rstd = rsqrtf(var + 1e-12f);

    float4 g = *(const float4*)(gamma + t * 4);
    float4 bb = *(const float4*)(beta + t * 4);
    float4 o = make_float4(dx * rstd * g.x + bb.x, dy * rstd * g.y + bb.y,
                           dz * rstd * g.z + bb.z, dw * rstd * g.w + bb.w);
    *(float4*)(out + base) = o;
}

// ---------------- launch ----------------
extern "C" void kernel_launch(void* const* d_in, const int* in_sizes, int n_in,
                              void* d_out, int out_size)
{
    const float* hidden    = (const float*)d_in[0];
    const float* attn_mask = (const float*)d_in[1];
    const float* head_mask = (const float*)d_in[2];
    const float* Wq = (const float*)d_in[3];
    const float* bq = (const float*)d_in[4];
    const float* Wk = (const float*)d_in[5];
    const float* bk = (const float*)d_in[6];
    const float* Wv = (const float*)d_in[7];
    const float* bv = (const float*)d_in[8];
    const float* Wo = (const float*)d_in[9];
    const float* bo = (const float*)d_in[10];
    const float* gamma = (const float*)d_in[11];
    const float* beta  = (const float*)d_in[12];
    float* out = (float*)d_out;

    void *pq, *pk, *pv, *pc, *pp, *ph, *pw;
    cudaGetSymbolAddress(&pq, g_q);
    cudaGetSymbolAddress(&pk, g_k);
    cudaGetSymbolAddress(&pv, g_v);
    cudaGetSymbolAddress(&pc, g_ctx);
    cudaGetSymbolAddress(&pp, g_proj);
    cudaGetSymbolAddress(&ph, g_hid);
    cudaGetSymbolAddress(&pw, g_wb);
    __nv_bfloat16* q   = (__nv_bfloat16*)pq;
    __nv_bfloat16* k   = (__nv_bfloat16*)pk;
    __nv_bfloat16* v   = (__nv_bfloat16*)pv;
    __nv_bfloat16* cx  = (__nv_bfloat16*)pc;
    float*         pr  = (float*)pp;
    __nv_bfloat16* hb  = (__nv_bfloat16*)ph;
    __nv_bfloat16* wb  = (__nv_bfloat16*)pw;

    const int FLASH_SMEM = 384 * FW * 4 + 4096;   // 59392 B
    const int GEMM_SMEM  = 2 * 3 * BUFB2;         // 61440 B
    static int attr_set = 0;
    if (!attr_set) {
        cudaFuncSetAttribute(flash_bf16_kernel,
                             cudaFuncAttributeMaxDynamicSharedMemorySize, FLASH_SMEM);
        cudaFuncSetAttribute(bf16_gemm_ca3<true>,
                             cudaFuncAttributeMaxDynamicSharedMemorySize, GEMM_SMEM);
        cudaFuncSetAttribute(bf16_gemm_ca3<false>,
                             cudaFuncAttributeMaxDynamicSharedMemorySize, GEMM_SMEM);
        attr_set = 1;
    }

    // fused pre-conversion: hidden + 4 weight matrices -> bf16
    cvt_all_kernel<<<HID_BLKS + 4 * W_BLKS, 256>>>(hidden, Wq, Wk, Wv, Wo, hb, wb);

    // fused QKV: q scaled by 0.125*log2e in epilogue (softmax exp2 domain)
    dim3 gQKV(ND / 128, NM / 128, 3);   // (6, 64, 3)
    bf16_gemm_ca3<true><<<gQKV, 256, GEMM_SMEM>>>(
        hb, wb, (long)WSZ, bq, bk, bv, q, k, v, ND, QSCALE, 1.0f, 1.0f);

    dim3 gF(NS / 128, NBH);             // (8, 96)
    flash_bf16_kernel<<<gF, 128, FLASH_SMEM>>>(q, k, v, attn_mask, head_mask, cx);

    dim3 gO(ND / 128, NM / 128, 1);     // (6, 64, 1)
    bf16_gemm_ca3<false><<<gO, 256, GEMM_SMEM>>>(
        cx, wb + 3 * WSZ, 0L, bo, bo, bo, pr, pr, pr, ND, 1.0f, 1.0f, 1.0f);

    ln_kernel<<<NM, 192>>>(pr, hidden, gamma, beta, out);
}